// round 6
// baseline (speedup 1.0000x reference)
#include <cuda_runtime.h>
#include <stdint.h>

#define Bn 32
#define In 1152
#define On 10
#define Dn 16
#define Hn 10
#define Sn 922
#define ROWF 20          // padded floats per u row (80B): conflict-free float4 LDS
#define NTHREADS 256

struct Smem {
    float u[In * ROWF];        // row-major, padded; float4-addressable
    float w[In];               // ||u_i||
    float w2[In];              // ||u_i||^2
    unsigned rbits[In];        // 10-bit hypothesis mask per i
    float Mu[Hn * 16];         // Mu[h][d]
    float mm[Hn];              // ||Mu_h||^2
    float denom[Hn];
    float npart[8 * 16 * Hn];  // per-warp num partials [w][d][h]
    float dpart[8 * Hn];       // per-warp denom partials
    float lpart[8 * Hn];       // per-warp loss partials
    float losses[Hn];
    int besth;
    int idx_is64;              // runtime dtype sniff for sample_idx
};

// sqrt via single MUFU.RSQ: x*rsqrt(x). x==0 -> 0 (0 * finite = 0 after clamp).
// ~22-bit accurate; tolerance is 1e-3.
__device__ __forceinline__ float fsqrt_mufu(float x) {
    return x * __frsqrt_rn(fmaxf(x, 1e-35f));
}

__global__ void __launch_bounds__(NTHREADS, 2)
ransac_kernel(const float* __restrict__ up, const int* __restrict__ sidx32,
              float* __restrict__ out)
{
    extern __shared__ float smraw[];
    Smem* sm = reinterpret_cast<Smem*>(smraw);
    const int tid = threadIdx.x;
    const int bo = blockIdx.x;
    const int b = bo / On, o = bo % On;
    const int lane = tid & 31, wrp = tid >> 5;

    // ---- zero hypothesis masks; sniff index dtype ----
    for (int i = tid; i < In; i += NTHREADS) sm->rbits[i] = 0u;
    if (tid == 0) {
        // int64 -> odd 32-bit words (high halves) are all 0 for idx in [0,1152)
        int all0 = 1;
        #pragma unroll
        for (int k = 0; k < 8; k++) all0 &= (sidx32[2 * k + 1] == 0);
        sm->idx_is64 = all0;
    }
    __syncthreads();
    const int is64 = sm->idx_is64;

    float4* u4 = reinterpret_cast<float4*>(sm->u);

    // ---- Phases A (warps 0-2) and C (warps 3-7) run CONCURRENTLY ----
    if (tid < 96) {
        // Phase A: load u slice into smem (padded rows), fused norm compute.
        // u_predict[b,i,o,d] at b*I*O*D + i*O*D + o*D + d
        const float4* ub = reinterpret_cast<const float4*>(up + ((size_t)b * In * On + o) * Dn);
        #pragma unroll
        for (int k = 0; k < (In * 4) / 96; k++) {             // 48 exact iters
            int e = tid + k * 96;
            int i = e >> 2, q = e & 3;
            float4 v = ub[i * 40 + q];                         // O*D/4 = 40
            u4[i * 5 + q] = v;                                 // ROWF/4 = 5
            float s = v.x * v.x + v.y * v.y + v.z * v.z + v.w * v.w;
            s += __shfl_xor_sync(0xffffffffu, s, 1);
            s += __shfl_xor_sync(0xffffffffu, s, 2);
            if (q == 0) { sm->w2[i] = s; sm->w[i] = fsqrt_mufu(s); }
        }
    } else {
        // Phase C: scatter sample_idx -> rbits (atomicOr: commutative, deterministic)
        // sample_idx[b,s,o,h] element offset: b*S*O*H + s*O*H + o*H + h
        const size_t base = (size_t)b * Sn * On * Hn + (size_t)o * Hn;
        const int ct = tid - 96;                               // 0..159
        for (int e = ct; e < Sn * Hn; e += 160) {
            int s = e / Hn, h = e - s * Hn;
            size_t eo = base + (size_t)s * (On * Hn) + h;
            int i = is64 ? sidx32[eo << 1] : sidx32[eo];       // int64: low word (LE)
            if ((unsigned)i < (unsigned)In)                    // never fault
                atomicOr(&sm->rbits[i], 1u << h);
        }
    }
    __syncthreads();

    // ---- Phase D: num[d][h] = sum_i r*w*u ; denom[h] = sum_i r*w ----
    {
        const int q = tid & 3, ip = tid >> 2;                 // d-quad, i-partition
        float acc[4][Hn], dloc[Hn];
        #pragma unroll
        for (int h = 0; h < Hn; h++) {
            acc[0][h] = 0.f; acc[1][h] = 0.f; acc[2][h] = 0.f; acc[3][h] = 0.f;
            dloc[h] = 0.f;
        }
        #pragma unroll 3
        for (int i = ip; i < In; i += 64) {                   // 18 exact iters
            float4 uq = u4[i * 5 + q];
            unsigned bits = sm->rbits[i];
            float wi = sm->w[i];
            #pragma unroll
            for (int h = 0; h < Hn; h++) {
                float m = ((bits >> h) & 1u) ? wi : 0.0f;
                acc[0][h] = fmaf(m, uq.x, acc[0][h]);
                acc[1][h] = fmaf(m, uq.y, acc[1][h]);
                acc[2][h] = fmaf(m, uq.z, acc[2][h]);
                acc[3][h] = fmaf(m, uq.w, acc[3][h]);
                dloc[h] += m;
            }
        }
        // reduce over the 8 i-partitions within each warp (q preserved)
        #pragma unroll
        for (int off = 4; off <= 16; off <<= 1) {
            #pragma unroll
            for (int h = 0; h < Hn; h++) {
                acc[0][h] += __shfl_xor_sync(0xffffffffu, acc[0][h], off);
                acc[1][h] += __shfl_xor_sync(0xffffffffu, acc[1][h], off);
                acc[2][h] += __shfl_xor_sync(0xffffffffu, acc[2][h], off);
                acc[3][h] += __shfl_xor_sync(0xffffffffu, acc[3][h], off);
                dloc[h]   += __shfl_xor_sync(0xffffffffu, dloc[h], off);
            }
        }
        if (lane < 4) {                                       // one lane per q
            #pragma unroll
            for (int j = 0; j < 4; j++)
                #pragma unroll
                for (int h = 0; h < Hn; h++)
                    sm->npart[(wrp * 16 + (q * 4 + j)) * Hn + h] = acc[j][h];
            if (q == 0)
                #pragma unroll
                for (int h = 0; h < Hn; h++) sm->dpart[wrp * Hn + h] = dloc[h];
        }
    }
    __syncthreads();

    // ---- Phase E: final reduce -> Mu, mm ----
    float numreg = 0.f;
    int dd = 0, hh = 0;
    if (tid < 160) {
        dd = tid / Hn; hh = tid - dd * Hn;
        #pragma unroll
        for (int w8 = 0; w8 < 8; w8++) numreg += sm->npart[(w8 * 16 + dd) * Hn + hh];
    } else if (tid < 160 + Hn) {
        int h = tid - 160;
        float s = 0.f;
        #pragma unroll
        for (int w8 = 0; w8 < 8; w8++) s += sm->dpart[w8 * Hn + h];
        sm->denom[h] = s;
    }
    __syncthreads();
    if (tid < 160) sm->Mu[hh * 16 + dd] = numreg / sm->denom[hh];
    __syncthreads();
    if (tid < Hn) {
        float s = 0.f;
        #pragma unroll
        for (int d = 0; d < Dn; d++) { float m = sm->Mu[tid * 16 + d]; s = fmaf(m, m, s); }
        sm->mm[tid] = s;
    }
    __syncthreads();

    // ---- Phase F: losses[h] = sum_i sqrt(w2[i] - 2*dot(u_i,Mu_h) + mm[h]) ----
    {
        float lloc[Hn];
        float mmr[Hn];
        #pragma unroll
        for (int h = 0; h < Hn; h++) { lloc[h] = 0.f; mmr[h] = sm->mm[h]; }
        const float4* mu4 = reinterpret_cast<const float4*>(sm->Mu);
        for (int i = tid; i < In; i += NTHREADS) {
            float4 a = u4[i * 5 + 0], bb = u4[i * 5 + 1];
            float4 c = u4[i * 5 + 2], d4 = u4[i * 5 + 3];
            float ww2 = sm->w2[i];
            #pragma unroll
            for (int h = 0; h < Hn; h++) {
                float4 m0 = mu4[h * 4 + 0], m1 = mu4[h * 4 + 1];
                float4 m2 = mu4[h * 4 + 2], m3 = mu4[h * 4 + 3];
                // two independent FMA chains -> shorter dep path
                float d0 = a.x * m0.x;
                float d1 = a.y * m0.y;
                d0 = fmaf(a.z, m0.z, d0);   d1 = fmaf(a.w, m0.w, d1);
                d0 = fmaf(bb.x, m1.x, d0);  d1 = fmaf(bb.y, m1.y, d1);
                d0 = fmaf(bb.z, m1.z, d0);  d1 = fmaf(bb.w, m1.w, d1);
                d0 = fmaf(c.x, m2.x, d0);   d1 = fmaf(c.y, m2.y, d1);
                d0 = fmaf(c.z, m2.z, d0);   d1 = fmaf(c.w, m2.w, d1);
                d0 = fmaf(d4.x, m3.x, d0);  d1 = fmaf(d4.y, m3.y, d1);
                d0 = fmaf(d4.z, m3.z, d0);  d1 = fmaf(d4.w, m3.w, d1);
                float s = fmaf(-2.0f, d0 + d1, ww2 + mmr[h]);
                s = fmaxf(s, 0.0f);
                lloc[h] += fsqrt_mufu(s);                      // MUFU.RSQ path
            }
        }
        #pragma unroll
        for (int off = 1; off <= 16; off <<= 1)
            #pragma unroll
            for (int h = 0; h < Hn; h++)
                lloc[h] += __shfl_xor_sync(0xffffffffu, lloc[h], off);
        if (lane == 0)
            #pragma unroll
            for (int h = 0; h < Hn; h++) sm->lpart[wrp * Hn + h] = lloc[h];
    }
    __syncthreads();
    if (tid < Hn) {
        float s = 0.f;
        #pragma unroll
        for (int w8 = 0; w8 < 8; w8++) s += sm->lpart[w8 * Hn + tid];
        sm->losses[tid] = s;
    }
    __syncthreads();
    if (tid == 0) {
        int best = 0; float bv = sm->losses[0];
        #pragma unroll
        for (int h = 1; h < Hn; h++)
            if (sm->losses[h] < bv) { bv = sm->losses[h]; best = h; }
        sm->besth = best;
    }
    __syncthreads();

    // ---- output: v[b,o,:] = Mu[:, besth] ----
    if (tid < Dn)
        out[((size_t)b * On + o) * Dn + tid] = sm->Mu[sm->besth * 16 + tid];
}

extern "C" void kernel_launch(void* const* d_in, const int* in_sizes, int n_in,
                              void* d_out, int out_size)
{
    const float* up;
    const int* si;
    if (in_sizes[0] == Bn * In * On * Dn) {
        up = (const float*)d_in[0];
        si = (const int*)d_in[1];
    } else {
        up = (const float*)d_in[1];
        si = (const int*)d_in[0];
    }
    float* out = (float*)d_out;

    cudaFuncSetAttribute(ransac_kernel,
                         cudaFuncAttributeMaxDynamicSharedMemorySize,
                         (int)sizeof(Smem));
    ransac_kernel<<<Bn * On, NTHREADS, sizeof(Smem)>>>(up, si, out);
}

// round 7
// speedup vs baseline: 1.1483x; 1.1483x over previous
#include <cuda_runtime.h>
#include <stdint.h>

#define Bn 32
#define In 1152
#define On 10
#define Dn 16
#define Hn 10
#define Sn 922
#define NTHREADS 256
#define NBO (Bn * On)            // 320 (b,o) tasks

// ---- global scratch (device globals: allocation-free) ----
__device__ float g_uprime[(size_t)NBO * In * Dn];   // [bo][i][d]  5.9 MB
__device__ float g_w [(size_t)NBO * In];            // ||u_i||     1.5 MB
__device__ float g_w2[(size_t)NBO * In];            // ||u_i||^2   1.5 MB

// sqrt via single MUFU.RSQ: x*rsqrt(x). clamp keeps 0 -> 0.
__device__ __forceinline__ float fsqrt_mufu(float x) {
    return x * __frsqrt_rn(fmaxf(x, 1e-35f));
}

// ================= K0: transpose + norms =================
// src-linear float4 indexing: perfectly coalesced reads.
__global__ void __launch_bounds__(NTHREADS)
prep_kernel(const float* __restrict__ up)
{
    int e = blockIdx.x * NTHREADS + threadIdx.x;    // float4 id over whole tensor
    int q = e & 3;
    int t = e >> 2;                                  // (b*I + i)*O + o
    int o = t % On;
    int bi = t / On;
    int i = bi % In;
    int b = bi / In;
    float4 v = reinterpret_cast<const float4*>(up)[e];
    int bo = b * On + o;
    reinterpret_cast<float4*>(g_uprime)[((size_t)bo * In + i) * 4 + q] = v;
    float s = v.x * v.x + v.y * v.y + v.z * v.z + v.w * v.w;
    s += __shfl_xor_sync(0xffffffffu, s, 1);
    s += __shfl_xor_sync(0xffffffffu, s, 2);
    if (q == 0) {
        size_t off = (size_t)bo * In + i;
        g_w2[off] = s;
        g_w[off]  = fsqrt_mufu(s);
    }
}

// ================= K1: main =================
struct SmemK1 {
    unsigned rbits[In];          // 10-bit hypothesis mask per i
    float npart[8 * Dn * Hn];    // per-warp num partials [w][d][h]
    float dpart[8 * Hn];
    float lpart[8 * Hn];
    float Mu[Hn * Dn];           // Mu[h][d]
    float mm[Hn];
    float denom[Hn];
    float losses[Hn];
    int besth;
    int idx_is64;
};

__global__ void __launch_bounds__(NTHREADS, 4)
ransac_kernel(const int* __restrict__ sidx32, float* __restrict__ out)
{
    __shared__ SmemK1 sm;
    const int tid = threadIdx.x;
    const int bo = blockIdx.x;
    const int b = bo / On, o = bo % On;
    const int lane = tid & 31, wrp = tid >> 5;

    const float*  uP  = g_uprime + (size_t)bo * In * Dn;
    const float4* u4  = reinterpret_cast<const float4*>(uP);
    const float*  wP  = g_w  + (size_t)bo * In;
    const float*  w2P = g_w2 + (size_t)bo * In;

    // ---- init: zero masks; sniff index dtype ----
    for (int i = tid; i < In; i += NTHREADS) sm.rbits[i] = 0u;
    if (tid == 0) {
        int all0 = 1;                       // int64 -> odd words all 0 (idx < 1152)
        #pragma unroll
        for (int k = 0; k < 8; k++) all0 &= (sidx32[2 * k + 1] == 0);
        sm.idx_is64 = all0;
    }
    __syncthreads();
    const int is64 = sm.idx_is64;

    // ---- Phase C: scatter sample_idx -> rbits (full block) ----
    {
        const size_t base = (size_t)b * Sn * On * Hn + (size_t)o * Hn;
        for (int e = tid; e < Sn * Hn; e += NTHREADS) {
            int s = e / Hn, h = e - s * Hn;
            size_t eo = base + (size_t)s * (On * Hn) + h;
            int i = is64 ? sidx32[eo << 1] : sidx32[eo];   // low word (LE)
            if ((unsigned)i < (unsigned)In)
                atomicOr(&sm.rbits[i], 1u << h);
        }
    }
    __syncthreads();

    // ---- Phase D: num[d][h] = sum_i r*w*u ; denom[h] = sum_i r*w ----
    // d-pair split: lane handles dims {d8, d8+8}, 32 i-partitions.
    {
        const int d8 = tid & 7, ip = tid >> 3;
        float acc0[Hn], acc1[Hn], dloc[Hn];
        #pragma unroll
        for (int h = 0; h < Hn; h++) { acc0[h] = 0.f; acc1[h] = 0.f; dloc[h] = 0.f; }
        #pragma unroll 4
        for (int i = ip; i < In; i += 32) {                 // 36 exact iters
            float ua = uP[i * Dn + d8];
            float ub = uP[i * Dn + d8 + 8];
            unsigned bits = sm.rbits[i];
            float wi = wP[i];
            #pragma unroll
            for (int h = 0; h < Hn; h++) {
                float m = ((bits >> h) & 1u) ? wi : 0.0f;
                acc0[h] = fmaf(m, ua, acc0[h]);
                acc1[h] = fmaf(m, ub, acc1[h]);
                dloc[h] += m;
            }
        }
        // reduce over the 4 ip-groups within the warp (d8 preserved)
        #pragma unroll
        for (int off = 8; off <= 16; off <<= 1) {
            #pragma unroll
            for (int h = 0; h < Hn; h++) {
                acc0[h] += __shfl_xor_sync(0xffffffffu, acc0[h], off);
                acc1[h] += __shfl_xor_sync(0xffffffffu, acc1[h], off);
                dloc[h] += __shfl_xor_sync(0xffffffffu, dloc[h], off);
            }
        }
        if (lane < 8) {
            #pragma unroll
            for (int h = 0; h < Hn; h++) {
                sm.npart[(wrp * Dn + d8) * Hn + h]     = acc0[h];
                sm.npart[(wrp * Dn + d8 + 8) * Hn + h] = acc1[h];
            }
            if (lane == 0)
                #pragma unroll
                for (int h = 0; h < Hn; h++) sm.dpart[wrp * Hn + h] = dloc[h];
        }
    }
    __syncthreads();

    // ---- Phase E: final reduce -> Mu, mm ----
    float numreg = 0.f;
    int dd = 0, hh = 0;
    if (tid < 160) {
        dd = tid / Hn; hh = tid - dd * Hn;
        #pragma unroll
        for (int w8 = 0; w8 < 8; w8++) numreg += sm.npart[(w8 * Dn + dd) * Hn + hh];
    } else if (tid < 160 + Hn) {
        int h = tid - 160;
        float s = 0.f;
        #pragma unroll
        for (int w8 = 0; w8 < 8; w8++) s += sm.dpart[w8 * Hn + h];
        sm.denom[h] = s;
    }
    __syncthreads();
    if (tid < 160) sm.Mu[hh * Dn + dd] = numreg / sm.denom[hh];
    __syncthreads();
    if (tid < Hn) {
        float s = 0.f;
        #pragma unroll
        for (int d = 0; d < Dn; d++) { float m = sm.Mu[tid * Dn + d]; s = fmaf(m, m, s); }
        sm.mm[tid] = s;
    }
    __syncthreads();

    // ---- Phase F: losses[h] = sum_i sqrt(w2[i] - 2*dot(u_i,Mu_h) + mm[h]) ----
    {
        float lloc[Hn], mmr[Hn];
        #pragma unroll
        for (int h = 0; h < Hn; h++) { lloc[h] = 0.f; mmr[h] = sm.mm[h]; }
        const float4* mu4 = reinterpret_cast<const float4*>(sm.Mu);
        for (int i = tid; i < In; i += NTHREADS) {
            float4 a  = u4[i * 4 + 0], b4 = u4[i * 4 + 1];
            float4 c  = u4[i * 4 + 2], d4 = u4[i * 4 + 3];
            float ww2 = w2P[i];
            #pragma unroll
            for (int h = 0; h < Hn; h++) {
                float4 m0 = mu4[h * 4 + 0], m1 = mu4[h * 4 + 1];
                float4 m2 = mu4[h * 4 + 2], m3 = mu4[h * 4 + 3];
                float d0 = a.x * m0.x;
                float d1 = a.y * m0.y;
                d0 = fmaf(a.z, m0.z, d0);   d1 = fmaf(a.w, m0.w, d1);
                d0 = fmaf(b4.x, m1.x, d0);  d1 = fmaf(b4.y, m1.y, d1);
                d0 = fmaf(b4.z, m1.z, d0);  d1 = fmaf(b4.w, m1.w, d1);
                d0 = fmaf(c.x, m2.x, d0);   d1 = fmaf(c.y, m2.y, d1);
                d0 = fmaf(c.z, m2.z, d0);   d1 = fmaf(c.w, m2.w, d1);
                d0 = fmaf(d4.x, m3.x, d0);  d1 = fmaf(d4.y, m3.y, d1);
                d0 = fmaf(d4.z, m3.z, d0);  d1 = fmaf(d4.w, m3.w, d1);
                float s = fmaf(-2.0f, d0 + d1, ww2 + mmr[h]);
                s = fmaxf(s, 0.0f);
                lloc[h] += fsqrt_mufu(s);
            }
        }
        #pragma unroll
        for (int off = 1; off <= 16; off <<= 1)
            #pragma unroll
            for (int h = 0; h < Hn; h++)
                lloc[h] += __shfl_xor_sync(0xffffffffu, lloc[h], off);
        if (lane == 0)
            #pragma unroll
            for (int h = 0; h < Hn; h++) sm.lpart[wrp * Hn + h] = lloc[h];
    }
    __syncthreads();
    if (tid < Hn) {
        float s = 0.f;
        #pragma unroll
        for (int w8 = 0; w8 < 8; w8++) s += sm.lpart[w8 * Hn + tid];
        sm.losses[tid] = s;
    }
    __syncthreads();
    if (tid == 0) {
        int best = 0; float bv = sm.losses[0];
        #pragma unroll
        for (int h = 1; h < Hn; h++)
            if (sm.losses[h] < bv) { bv = sm.losses[h]; best = h; }
        sm.besth = best;
    }
    __syncthreads();

    // ---- output: v[b,o,:] = Mu[:, besth] ----
    if (tid < Dn)
        out[(size_t)bo * Dn + tid] = sm.Mu[sm.besth * Dn + tid];
}

extern "C" void kernel_launch(void* const* d_in, const int* in_sizes, int n_in,
                              void* d_out, int out_size)
{
    const float* up;
    const int* si;
    if (in_sizes[0] == Bn * In * On * Dn) {
        up = (const float*)d_in[0];
        si = (const int*)d_in[1];
    } else {
        up = (const float*)d_in[1];
        si = (const int*)d_in[0];
    }
    float* out = (float*)d_out;

    // K0: transpose + norms.  total float4 = 320*1152*4 = 1,474,560 = 5760 * 256
    prep_kernel<<<(NBO * In * 4) / NTHREADS, NTHREADS>>>(up);
    // K1: main per-(b,o) kernel
    ransac_kernel<<<NBO, NTHREADS>>>(si, out);
}